// round 11
// baseline (speedup 1.0000x reference)
#include <cuda_runtime.h>
#include <cuda_fp16.h>
#include <cstdint>

#define HH 256
#define H2 512
#define GG 64
#define NNODE 20000
#define NEDGE 320000
#define NT 512                    // threads per GEMM CTA (16 warps, 4/SMSP)

#define WP 264                    // gemm1 W row halves (256 + 8 pad)
#define AP 264                    // A row halves
#define HP 520                    // gemm2 row halves (512 + 8 pad)
#define A_WS_BYTES (256 * WP * 2) // 135168
#define A_AS_BYTES (64 * AP * 2)  // 33792
#define A_SMEM (A_WS_BYTES + 2 * A_AS_BYTES)   // 202752
#define TM2 32
#define B_WS_BYTES (128 * HP * 2) // 133120
#define B_HS_BYTES (TM2 * HP * 2) // 33280
#define B_SMEM (B_WS_BYTES + 2 * B_HS_BYTES)   // 199680

// fp16 weights k-major: per readout [w1t: 512n x 256k][w2t: 256n x 512k]
__device__ __align__(16) __half g_w[3 * 262144];
__device__ __align__(16) float  g_gf[GG * HH];
__device__ __align__(16) __half g_a[(size_t)NEDGE * HH];   // LN(X) fp16
__device__ __align__(16) __half g_h[(size_t)NEDGE * H2];   // hidden fp16

// ---------- helpers ----------
__device__ __forceinline__ float gelu_fast(float x) {
    float u = x * (0.7978845608028654f + 0.035677408136300125f * x * x);
    float t;
    asm("tanh.approx.f32 %0, %1;" : "=f"(t) : "f"(u));
    return 0.5f * x * (1.0f + t);
}
__device__ __forceinline__ void hmma(float* c, const unsigned* a, unsigned b0, unsigned b1) {
    asm volatile(
        "mma.sync.aligned.m16n8k16.row.col.f32.f16.f16.f32 "
        "{%0,%1,%2,%3}, {%4,%5,%6,%7}, {%8,%9}, {%0,%1,%2,%3};\n"
        : "+f"(c[0]), "+f"(c[1]), "+f"(c[2]), "+f"(c[3])
        : "r"(a[0]), "r"(a[1]), "r"(a[2]), "r"(a[3]), "r"(b0), "r"(b1));
}
__device__ __forceinline__ void ldm4(unsigned r[4], unsigned a) {
    asm volatile("ldmatrix.sync.aligned.m8n8.x4.shared.b16 {%0,%1,%2,%3}, [%4];"
                 : "=r"(r[0]), "=r"(r[1]), "=r"(r[2]), "=r"(r[3]) : "r"(a));
}
#define CP_COMMIT asm volatile("cp.async.commit_group;\n")
#define CP_WAIT1  asm volatile("cp.async.wait_group 1;\n")
#define CP_WAIT0  asm volatile("cp.async.wait_group 0;\n")
__device__ __forceinline__ void cpa(unsigned dst, const void* src) {
    asm volatile("cp.async.cg.shared.global [%0], [%1], 16;\n" ::"r"(dst), "l"(src));
}

// ---------- prep: fp16 + transpose weights to k-major ----------
__global__ void prep_kernel(const float* __restrict__ n1, const float* __restrict__ n2,
                            const float* __restrict__ g1, const float* __restrict__ g2,
                            const float* __restrict__ e1, const float* __restrict__ e2) {
    int idx = blockIdx.x * blockDim.x + threadIdx.x;
    int rid = idx >> 18;
    int r = idx & 262143;
    const float* w1 = (rid == 0) ? n1 : (rid == 1) ? g1 : e1;
    const float* w2 = (rid == 0) ? n2 : (rid == 1) ? g2 : e2;
    float v;
    if (r < 131072) { int n = r >> 8, k = r & 255; v = w1[(size_t)k * H2 + n]; }
    else { int q = r - 131072; int n = q >> 9, k = q & 511; v = w2[(size_t)k * HH + n]; }
    g_w[idx] = __float2half_rn(v);
}

// ---------- segment mean (node_batch sorted) ----------
__global__ void seg_mean_kernel(const float* __restrict__ nf, const int* __restrict__ batch, int n) {
    int gid = blockIdx.x;
    int lo, hi;
    { int a = 0, b = n;  while (a < b) { int m = (a + b) >> 1; if (batch[m] <  gid) a = m + 1; else b = m; } lo = a; }
    { int a = lo, b = n; while (a < b) { int m = (a + b) >> 1; if (batch[m] <= gid) a = m + 1; else b = m; } hi = a; }
    int col = threadIdx.x;
    float s = 0.f;
    for (int r = lo; r < hi; ++r) s += nf[(size_t)r * HH + col];
    g_gf[gid * HH + col] = s / fmaxf((float)(hi - lo), 1.0f);
}

// ---------- LN pass: X -> g_a fp16, one warp per row ----------
__global__ void ln_kernel(const float* __restrict__ Xp, long R,
                          const float* __restrict__ gamma, const float* __restrict__ beta,
                          int use_gf) {
    const float* X = use_gf ? g_gf : Xp;
    int warp = threadIdx.x >> 5, lane = threadIdx.x & 31;
    long row = (long)blockIdx.x * 8 + warp;
    if (row >= R) return;
    float4 v0 = *(const float4*)(X + row * HH + lane * 8);
    float4 v1 = *(const float4*)(X + row * HH + lane * 8 + 4);
    float s = v0.x + v0.y + v0.z + v0.w + v1.x + v1.y + v1.z + v1.w;
    float q = v0.x * v0.x + v0.y * v0.y + v0.z * v0.z + v0.w * v0.w
            + v1.x * v1.x + v1.y * v1.y + v1.z * v1.z + v1.w * v1.w;
#pragma unroll
    for (int o = 16; o; o >>= 1) {
        s += __shfl_xor_sync(0xFFFFFFFFu, s, o);
        q += __shfl_xor_sync(0xFFFFFFFFu, q, o);
    }
    float mean = s * (1.0f / HH);
    float rstd = rsqrtf(q * (1.0f / HH) - mean * mean + 1e-5f);
    float4 gm0 = *(const float4*)(gamma + lane * 8);
    float4 gm1 = *(const float4*)(gamma + lane * 8 + 4);
    float4 bt0 = *(const float4*)(beta + lane * 8);
    float4 bt1 = *(const float4*)(beta + lane * 8 + 4);
    __half2 p0 = __floats2half2_rn((v0.x - mean) * rstd * gm0.x + bt0.x, (v0.y - mean) * rstd * gm0.y + bt0.y);
    __half2 p1 = __floats2half2_rn((v0.z - mean) * rstd * gm0.z + bt0.z, (v0.w - mean) * rstd * gm0.w + bt0.w);
    __half2 p2 = __floats2half2_rn((v1.x - mean) * rstd * gm1.x + bt1.x, (v1.y - mean) * rstd * gm1.y + bt1.y);
    __half2 p3 = __floats2half2_rn((v1.z - mean) * rstd * gm1.z + bt1.z, (v1.w - mean) * rstd * gm1.w + bt1.w);
    uint4 u;
    u.x = *(unsigned*)&p0; u.y = *(unsigned*)&p1; u.z = *(unsigned*)&p2; u.w = *(unsigned*)&p3;
    *(uint4*)(g_a + row * HH + lane * 8) = u;
}

// ---------- pass A: H = gelu(A @ w1half + b1) -> g_h (512 thr, 16 warps 4m x 4n) ----------
__global__ void __launch_bounds__(NT, 1)
gemm1_kernel(long R, int ntiles, int wbase, const float* __restrict__ bias1) {
    extern __shared__ char smem[];
    __half* Ws  = (__half*)smem;                       // 256n x WP
    __half* As0 = (__half*)(smem + A_WS_BYTES);        // 2 x 64 x AP
    int h = blockIdx.x, tid = threadIdx.x;
    int warp = tid >> 5, lane = tid & 31, g = lane >> 2, tig = lane & 3;
    int wm = warp >> 2, wn = warp & 3, m0 = wm * 16;
    unsigned ws_s = (unsigned)__cvta_generic_to_shared(Ws);
    unsigned as_s = (unsigned)__cvta_generic_to_shared(As0);

    {   // weight half load (once): 256 rows x 32 segs = 8192 cp / 512 = 16
        const __half* src = g_w + wbase + (size_t)h * 256 * 256;
#pragma unroll
        for (int it = 0; it < 16; ++it) {
            int idx = tid + it * NT;
            int row = idx >> 5, seg = idx & 31;
            cpa(ws_s + row * (WP * 2) + seg * 16, src + row * 256 + seg * 8);
        }
        CP_COMMIT;
    }
    // ldmatrix lane addressing
    int a_row = m0 + ((lane >> 3) & 1) * 8 + (lane & 7);
    int a_col = (lane >> 4) * 8;
    unsigned aoff = (unsigned)((a_row * AP + a_col) * 2);
    int b_n = wn * 64 + (lane >> 4) * 8 + (lane & 7);
    int b_col = ((lane >> 3) & 1) * 8;
    unsigned bbase = ws_s + (unsigned)((b_n * WP + b_col) * 2);

    long t = blockIdx.y;
    if (t < ntiles) {
#pragma unroll
        for (int it = 0; it < 4; ++it) {
            int idx = tid + it * NT;
            int row = idx >> 5, seg = idx & 31;
            cpa(as_s + row * (AP * 2) + seg * 16, g_a + ((size_t)t * 64 + row) * HH + seg * 8);
        }
        CP_COMMIT;
    }
    int buf = 0;
    for (; t < ntiles; t += gridDim.y, buf ^= 1) {
        long tn = t + gridDim.y;
        if (tn < ntiles) {
            unsigned db = as_s + (buf ^ 1) * A_AS_BYTES;
#pragma unroll
            for (int it = 0; it < 4; ++it) {
                int idx = tid + it * NT;
                int row = idx >> 5, seg = idx & 31;
                cpa(db + row * (AP * 2) + seg * 16, g_a + ((size_t)tn * 64 + row) * HH + seg * 8);
            }
            CP_COMMIT; CP_WAIT1;
        } else { CP_WAIT0; }
        __syncthreads();

        unsigned abuf = as_s + buf * A_AS_BYTES;
        float acc[8][4];
#pragma unroll
        for (int nt = 0; nt < 8; ++nt)
#pragma unroll
            for (int i = 0; i < 4; ++i) acc[nt][i] = 0.f;
#pragma unroll 4
        for (int kt = 0; kt < 16; ++kt) {
            unsigned koff = (unsigned)kt * 32;
            unsigned am[4];
            ldm4(am, abuf + aoff + koff);
#pragma unroll
            for (int gi = 0; gi < 4; ++gi) {
                unsigned b[4];
                ldm4(b, bbase + gi * (16 * WP * 2) + koff);
                hmma(acc[2 * gi],     am, b[0], b[1]);
                hmma(acc[2 * gi + 1], am, b[2], b[3]);
            }
        }
        __syncthreads();
        // GELU stage into As[buf]
        __half* Hst = As0 + buf * (A_AS_BYTES / 2);
#pragma unroll
        for (int nt = 0; nt < 8; ++nt) {
            int col = wn * 64 + nt * 8 + 2 * tig;
            float2 bb = *(const float2*)(bias1 + h * 256 + col);
            int r = m0 + g;
            *(__half2*)(Hst + r * AP + col) =
                __floats2half2_rn(gelu_fast(acc[nt][0] + bb.x),
                                  gelu_fast(acc[nt][1] + bb.y));
            *(__half2*)(Hst + (r + 8) * AP + col) =
                __floats2half2_rn(gelu_fast(acc[nt][2] + bb.x),
                                  gelu_fast(acc[nt][3] + bb.y));
        }
        __syncthreads();
        long base = t * 64;
#pragma unroll
        for (int it = 0; it < 4; ++it) {
            int idx = tid + it * NT;
            int row = idx >> 5, seg = idx & 31;
            if (base + row < R) {
                uint4 u = *(const uint4*)(Hst + row * AP + seg * 8);
                *(uint4*)(g_h + (base + row) * H2 + h * 256 + seg * 8) = u;
            }
        }
        __syncthreads();
    }
}

// ---------- pass B: out = H @ w2half + b2 + X (512 thr, 16 warps 2m x 8n) ----------
__global__ void __launch_bounds__(NT, 1)
gemm2_kernel(const float* __restrict__ Xp, long R, int ntiles, int wbase,
             const float* __restrict__ bias2, float* __restrict__ out, int use_gf) {
    extern __shared__ char smem[];
    __half* Ws = (__half*)smem;                  // 128n x HP
    __half* Hs = (__half*)(smem + B_WS_BYTES);   // 2 x 32 x HP
    const float* X = use_gf ? g_gf : Xp;
    int h = blockIdx.x, tid = threadIdx.x;
    int warp = tid >> 5, lane = tid & 31, g = lane >> 2, tig = lane & 3;
    int wm = warp >> 3, wn = warp & 7, m0 = wm * 16;
    unsigned ws_s = (unsigned)__cvta_generic_to_shared(Ws);
    unsigned hs_s = (unsigned)__cvta_generic_to_shared(Hs);

    {   // w2 half load (once): 128 rows x 64 segs = 8192 / 512 = 16
        const __half* src = g_w + wbase + 131072 + (size_t)h * 128 * 512;
#pragma unroll
        for (int it = 0; it < 16; ++it) {
            int idx = tid + it * NT;
            int row = idx >> 6, seg = idx & 63;
            cpa(ws_s + row * (HP * 2) + seg * 16, src + row * 512 + seg * 8);
        }
        CP_COMMIT;
    }
    int a_row = m0 + ((lane >> 3) & 1) * 8 + (lane & 7);
    int a_col = (lane >> 4) * 8;
    unsigned aoff = (unsigned)((a_row * HP + a_col) * 2);
    int b_n = wn * 16 + (lane >> 4) * 8 + (lane & 7);
    int b_col = ((lane >> 3) & 1) * 8;
    unsigned bbase = ws_s + (unsigned)((b_n * HP + b_col) * 2);

    long t = blockIdx.y;
    if (t < ntiles) {
#pragma unroll
        for (int it = 0; it < 4; ++it) {
            int idx = tid + it * NT;
            int row = idx >> 6, seg = idx & 63;
            cpa(hs_s + row * (HP * 2) + seg * 16, g_h + ((size_t)t * TM2 + row) * H2 + seg * 8);
        }
        CP_COMMIT;
    }
    int buf = 0;
    for (; t < ntiles; t += gridDim.y, buf ^= 1) {
        long tn = t + gridDim.y;
        if (tn < ntiles) {
            unsigned db = hs_s + (buf ^ 1) * B_HS_BYTES;
#pragma unroll
            for (int it = 0; it < 4; ++it) {
                int idx = tid + it * NT;
                int row = idx >> 6, seg = idx & 63;
                cpa(db + row * (HP * 2) + seg * 16, g_h + ((size_t)tn * TM2 + row) * H2 + seg * 8);
            }
            CP_COMMIT; CP_WAIT1;
        } else { CP_WAIT0; }
        __syncthreads();

        unsigned hbuf = hs_s + buf * B_HS_BYTES;
        float acc[2][4];
#pragma unroll
        for (int nt = 0; nt < 2; ++nt)
#pragma unroll
            for (int i = 0; i < 4; ++i) acc[nt][i] = 0.f;
#pragma unroll 8
        for (int kt = 0; kt < 32; ++kt) {
            unsigned koff = (unsigned)kt * 32;
            unsigned a[4], b[4];
            ldm4(a, hbuf + aoff + koff);
            ldm4(b, bbase + koff);
            hmma(acc[0], a, b[0], b[1]);
            hmma(acc[1], a, b[2], b[3]);
        }
        // epilogue: bias + residual
        long base = t * TM2;
#pragma unroll
        for (int nt = 0; nt < 2; ++nt) {
            int col = h * 128 + wn * 16 + nt * 8 + 2 * tig;
            float2 bb = *(const float2*)(bias2 + col);
            int r = m0 + g;
            long gr0 = base + r, gr1 = gr0 + 8;
            if (gr0 < R) {
                float2 x = *(const float2*)(X + gr0 * HH + col);
                *(float2*)(out + gr0 * HH + col) =
                    make_float2(acc[nt][0] + bb.x + x.x, acc[nt][1] + bb.y + x.y);
            }
            if (gr1 < R) {
                float2 x = *(const float2*)(X + gr1 * HH + col);
                *(float2*)(out + gr1 * HH + col) =
                    make_float2(acc[nt][2] + bb.x + x.x, acc[nt][3] + bb.y + x.y);
            }
        }
        __syncthreads();
    }
}

// ---------- launch ----------
extern "C" void kernel_launch(void* const* d_in, const int* in_sizes, int n_in,
                              void* d_out, int out_size) {
    const float* nodef = (const float*)d_in[0];
    const float* edgef = (const float*)d_in[1];
    const int*   batch = (const int*)d_in[2];
    int pb = n_in - 18;
    const float* P[18];
    for (int i = 0; i < 18; ++i) P[i] = (const float*)d_in[pb + i];

    float* out   = (float*)d_out;
    float* out_g = out;
    float* out_n = out + (size_t)GG * HH;
    float* out_e = out_n + (size_t)NNODE * HH;

    cudaFuncSetAttribute(gemm1_kernel, cudaFuncAttributeMaxDynamicSharedMemorySize, A_SMEM);
    cudaFuncSetAttribute(gemm2_kernel, cudaFuncAttributeMaxDynamicSharedMemorySize, B_SMEM);

    prep_kernel<<<3072, 256>>>(P[2], P[4], P[8], P[10], P[14], P[16]);
    seg_mean_kernel<<<GG, HH>>>(nodef, batch, NNODE);

    // node
    ln_kernel<<<(NNODE + 7) / 8, 256>>>(nodef, NNODE, P[0], P[1], 0);
    gemm1_kernel<<<dim3(2, 74), NT, A_SMEM>>>(NNODE, 313, 0, P[3]);
    gemm2_kernel<<<dim3(2, 74), NT, B_SMEM>>>(nodef, NNODE, 625, 0, P[5], out_n, 0);
    // global
    ln_kernel<<<8, 256>>>(nullptr, GG, P[6], P[7], 1);
    gemm1_kernel<<<dim3(2, 1), NT, A_SMEM>>>(GG, 1, 262144, P[9]);
    gemm2_kernel<<<dim3(2, 2), NT, B_SMEM>>>(nullptr, GG, 2, 262144, P[11], out_g, 1);
    // edge
    ln_kernel<<<NEDGE / 8, 256>>>(edgef, NEDGE, P[12], P[13], 0);
    gemm1_kernel<<<dim3(2, 74), NT, A_SMEM>>>(NEDGE, 5000, 524288, P[15]);
    gemm2_kernel<<<dim3(2, 74), NT, B_SMEM>>>(edgef, NEDGE, 10000, 524288, P[17], out_e, 0);
}

// round 12
// speedup vs baseline: 1.1088x; 1.1088x over previous
#include <cuda_runtime.h>
#include <cuda_fp16.h>
#include <cstdint>

#define HH 256
#define H2 512
#define GG 64
#define NNODE 20000
#define NEDGE 320000
#define NT 128                    // 4 warps per GEMM CTA, 1 per SMSP

#define WP 264                    // gemm1 W row halves (256 + 8 pad)
#define AP 264                    // A row halves
#define HP 520                    // gemm2 row halves (512 + 8 pad)
#define A_WS_BYTES (256 * WP * 2) // 135168
#define A_AS_BYTES (64 * AP * 2)  // 33792
#define A_SMEM (A_WS_BYTES + 2 * A_AS_BYTES)   // 202752
#define TM2 32
#define B_WS_BYTES (128 * HP * 2) // 133120
#define B_HS_BYTES (TM2 * HP * 2) // 33280
#define B_SMEM (B_WS_BYTES + 2 * B_HS_BYTES)   // 199680

// fp16 weights k-major: per readout [w1t: 512n x 256k][w2t: 256n x 512k]
__device__ __align__(16) __half g_w[3 * 262144];
__device__ __align__(16) float  g_gf[GG * HH];
__device__ __align__(16) __half g_a[(size_t)NEDGE * HH];   // LN(X) fp16
__device__ __align__(16) __half g_h[(size_t)NEDGE * H2];   // hidden fp16

// ---------- helpers ----------
__device__ __forceinline__ float gelu_fast(float x) {
    float u = x * (0.7978845608028654f + 0.035677408136300125f * x * x);
    float t;
    asm("tanh.approx.f32 %0, %1;" : "=f"(t) : "f"(u));
    return 0.5f * x * (1.0f + t);
}
__device__ __forceinline__ void hmma(float* c, const unsigned* a, unsigned b0, unsigned b1) {
    asm volatile(
        "mma.sync.aligned.m16n8k16.row.col.f32.f16.f16.f32 "
        "{%0,%1,%2,%3}, {%4,%5,%6,%7}, {%8,%9}, {%0,%1,%2,%3};\n"
        : "+f"(c[0]), "+f"(c[1]), "+f"(c[2]), "+f"(c[3])
        : "r"(a[0]), "r"(a[1]), "r"(a[2]), "r"(a[3]), "r"(b0), "r"(b1));
}
__device__ __forceinline__ void ldm4(unsigned r[4], unsigned a) {
    asm volatile("ldmatrix.sync.aligned.m8n8.x4.shared.b16 {%0,%1,%2,%3}, [%4];"
                 : "=r"(r[0]), "=r"(r[1]), "=r"(r[2]), "=r"(r[3]) : "r"(a));
}
#define CP_COMMIT asm volatile("cp.async.commit_group;\n")
#define CP_WAIT1  asm volatile("cp.async.wait_group 1;\n")
#define CP_WAIT0  asm volatile("cp.async.wait_group 0;\n")
__device__ __forceinline__ void cpa(unsigned dst, const void* src) {
    asm volatile("cp.async.cg.shared.global [%0], [%1], 16;\n" ::"r"(dst), "l"(src));
}

// ---------- prep: fp16 + transpose weights to k-major ----------
__global__ void prep_kernel(const float* __restrict__ n1, const float* __restrict__ n2,
                            const float* __restrict__ g1, const float* __restrict__ g2,
                            const float* __restrict__ e1, const float* __restrict__ e2) {
    int idx = blockIdx.x * blockDim.x + threadIdx.x;
    int rid = idx >> 18;
    int r = idx & 262143;
    const float* w1 = (rid == 0) ? n1 : (rid == 1) ? g1 : e1;
    const float* w2 = (rid == 0) ? n2 : (rid == 1) ? g2 : e2;
    float v;
    if (r < 131072) { int n = r >> 8, k = r & 255; v = w1[(size_t)k * H2 + n]; }
    else { int q = r - 131072; int n = q >> 9, k = q & 511; v = w2[(size_t)k * HH + n]; }
    g_w[idx] = __float2half_rn(v);
}

// ---------- segment mean (node_batch sorted) ----------
__global__ void seg_mean_kernel(const float* __restrict__ nf, const int* __restrict__ batch, int n) {
    int gid = blockIdx.x;
    int lo, hi;
    { int a = 0, b = n;  while (a < b) { int m = (a + b) >> 1; if (batch[m] <  gid) a = m + 1; else b = m; } lo = a; }
    { int a = lo, b = n; while (a < b) { int m = (a + b) >> 1; if (batch[m] <= gid) a = m + 1; else b = m; } hi = a; }
    int col = threadIdx.x;
    float s = 0.f;
    for (int r = lo; r < hi; ++r) s += nf[(size_t)r * HH + col];
    g_gf[gid * HH + col] = s / fmaxf((float)(hi - lo), 1.0f);
}

// ---------- LN pass: X -> g_a fp16, one warp per row ----------
__global__ void ln_kernel(const float* __restrict__ Xp, long R,
                          const float* __restrict__ gamma, const float* __restrict__ beta,
                          int use_gf) {
    const float* X = use_gf ? g_gf : Xp;
    int warp = threadIdx.x >> 5, lane = threadIdx.x & 31;
    long row = (long)blockIdx.x * 8 + warp;
    if (row >= R) return;
    float4 v0 = *(const float4*)(X + row * HH + lane * 8);
    float4 v1 = *(const float4*)(X + row * HH + lane * 8 + 4);
    float s = v0.x + v0.y + v0.z + v0.w + v1.x + v1.y + v1.z + v1.w;
    float q = v0.x * v0.x + v0.y * v0.y + v0.z * v0.z + v0.w * v0.w
            + v1.x * v1.x + v1.y * v1.y + v1.z * v1.z + v1.w * v1.w;
#pragma unroll
    for (int o = 16; o; o >>= 1) {
        s += __shfl_xor_sync(0xFFFFFFFFu, s, o);
        q += __shfl_xor_sync(0xFFFFFFFFu, q, o);
    }
    float mean = s * (1.0f / HH);
    float rstd = rsqrtf(q * (1.0f / HH) - mean * mean + 1e-5f);
    float4 gm0 = *(const float4*)(gamma + lane * 8);
    float4 gm1 = *(const float4*)(gamma + lane * 8 + 4);
    float4 bt0 = *(const float4*)(beta + lane * 8);
    float4 bt1 = *(const float4*)(beta + lane * 8 + 4);
    __half2 p0 = __floats2half2_rn((v0.x - mean) * rstd * gm0.x + bt0.x, (v0.y - mean) * rstd * gm0.y + bt0.y);
    __half2 p1 = __floats2half2_rn((v0.z - mean) * rstd * gm0.z + bt0.z, (v0.w - mean) * rstd * gm0.w + bt0.w);
    __half2 p2 = __floats2half2_rn((v1.x - mean) * rstd * gm1.x + bt1.x, (v1.y - mean) * rstd * gm1.y + bt1.y);
    __half2 p3 = __floats2half2_rn((v1.z - mean) * rstd * gm1.z + bt1.z, (v1.w - mean) * rstd * gm1.w + bt1.w);
    uint4 u;
    u.x = *(unsigned*)&p0; u.y = *(unsigned*)&p1; u.z = *(unsigned*)&p2; u.w = *(unsigned*)&p3;
    *(uint4*)(g_a + row * HH + lane * 8) = u;
}

// ---------- pass A: H = gelu(A @ w1half + b1) -> g_h (4 warps, warp tile 64m x 64n) ----------
__global__ void __launch_bounds__(NT, 1)
gemm1_kernel(long R, int ntiles, int wbase, const float* __restrict__ bias1) {
    extern __shared__ char smem[];
    __half* Ws  = (__half*)smem;                       // 256n x WP
    __half* As0 = (__half*)(smem + A_WS_BYTES);        // 2 x 64 x AP
    int h = blockIdx.x, tid = threadIdx.x;
    int warp = tid >> 5, lane = tid & 31, g = lane >> 2, tig = lane & 3;
    int wn = warp;                                     // 1m x 4n
    unsigned ws_s = (unsigned)__cvta_generic_to_shared(Ws);
    unsigned as_s = (unsigned)__cvta_generic_to_shared(As0);

    {   // weight half load (once): 8192 cp / 128 = 64
        const __half* src = g_w + wbase + (size_t)h * 256 * 256;
#pragma unroll
        for (int it = 0; it < 64; ++it) {
            int idx = tid + it * NT;
            int row = idx >> 5, seg = idx & 31;
            cpa(ws_s + row * (WP * 2) + seg * 16, src + row * 256 + seg * 8);
        }
        CP_COMMIT;
    }
    // ldmatrix lane addressing
    int a_row = ((lane >> 3) & 1) * 8 + (lane & 7);
    int a_col = (lane >> 4) * 8;
    unsigned aoff = (unsigned)((a_row * AP + a_col) * 2);
    int b_n = wn * 64 + (lane >> 4) * 8 + (lane & 7);
    int b_col = ((lane >> 3) & 1) * 8;
    unsigned bbase = ws_s + (unsigned)((b_n * WP + b_col) * 2);

    long t = blockIdx.y;
    if (t < ntiles) {
#pragma unroll
        for (int it = 0; it < 16; ++it) {
            int idx = tid + it * NT;
            int row = idx >> 5, seg = idx & 31;
            cpa(as_s + row * (AP * 2) + seg * 16, g_a + ((size_t)t * 64 + row) * HH + seg * 8);
        }
        CP_COMMIT;
    }
    int buf = 0;
    for (; t < ntiles; t += gridDim.y, buf ^= 1) {
        long tn = t + gridDim.y;
        if (tn < ntiles) {
            unsigned db = as_s + (buf ^ 1) * A_AS_BYTES;
#pragma unroll
            for (int it = 0; it < 16; ++it) {
                int idx = tid + it * NT;
                int row = idx >> 5, seg = idx & 31;
                cpa(db + row * (AP * 2) + seg * 16, g_a + ((size_t)tn * 64 + row) * HH + seg * 8);
            }
            CP_COMMIT; CP_WAIT1;
        } else { CP_WAIT0; }
        __syncthreads();

        unsigned abuf = as_s + buf * A_AS_BYTES;
        float acc[4][8][4];
#pragma unroll
        for (int mi = 0; mi < 4; ++mi)
#pragma unroll
            for (int nt = 0; nt < 8; ++nt)
#pragma unroll
                for (int i = 0; i < 4; ++i) acc[mi][nt][i] = 0.f;
#pragma unroll 2
        for (int kt = 0; kt < 16; ++kt) {
            unsigned koff = (unsigned)kt * 32;
            unsigned a[4][4], b[4][4];
#pragma unroll
            for (int mi = 0; mi < 4; ++mi)
                ldm4(a[mi], abuf + aoff + mi * (16 * AP * 2) + koff);
#pragma unroll
            for (int ni = 0; ni < 4; ++ni)
                ldm4(b[ni], bbase + ni * (16 * WP * 2) + koff);
#pragma unroll
            for (int mi = 0; mi < 4; ++mi)
#pragma unroll
                for (int ni = 0; ni < 4; ++ni) {
                    hmma(acc[mi][2 * ni],     a[mi], b[ni][0], b[ni][1]);
                    hmma(acc[mi][2 * ni + 1], a[mi], b[ni][2], b[ni][3]);
                }
        }
        __syncthreads();
        // GELU stage into As[buf]
        __half* Hst = As0 + buf * (A_AS_BYTES / 2);
#pragma unroll
        for (int mi = 0; mi < 4; ++mi) {
            int r = mi * 16 + g;
#pragma unroll
            for (int nt = 0; nt < 8; ++nt) {
                int col = wn * 64 + nt * 8 + 2 * tig;
                float2 bb = *(const float2*)(bias1 + h * 256 + col);
                *(__half2*)(Hst + r * AP + col) =
                    __floats2half2_rn(gelu_fast(acc[mi][nt][0] + bb.x),
                                      gelu_fast(acc[mi][nt][1] + bb.y));
                *(__half2*)(Hst + (r + 8) * AP + col) =
                    __floats2half2_rn(gelu_fast(acc[mi][nt][2] + bb.x),
                                      gelu_fast(acc[mi][nt][3] + bb.y));
            }
        }
        __syncthreads();
        long base = t * 64;
#pragma unroll
        for (int it = 0; it < 16; ++it) {
            int idx = tid + it * NT;
            int row = idx >> 5, seg = idx & 31;
            if (base + row < R) {
                uint4 u = *(const uint4*)(Hst + row * AP + seg * 8);
                *(uint4*)(g_h + (base + row) * H2 + h * 256 + seg * 8) = u;
            }
        }
        __syncthreads();
    }
}

// ---------- pass B: out = H @ w2half + b2 + X (4 warps, warp tile 32m x 32n) ----------
__global__ void __launch_bounds__(NT, 1)
gemm2_kernel(const float* __restrict__ Xp, long R, int ntiles, int wbase,
             const float* __restrict__ bias2, float* __restrict__ out, int use_gf) {
    extern __shared__ char smem[];
    __half* Ws = (__half*)smem;                  // 128n x HP
    __half* Hs = (__half*)(smem + B_WS_BYTES);   // 2 x 32 x HP
    const float* X = use_gf ? g_gf : Xp;
    int h = blockIdx.x, tid = threadIdx.x;
    int warp = tid >> 5, lane = tid & 31, g = lane >> 2, tig = lane & 3;
    int wn = warp;                               // 1m x 4n
    unsigned ws_s = (unsigned)__cvta_generic_to_shared(Ws);
    unsigned hs_s = (unsigned)__cvta_generic_to_shared(Hs);

    {   // w2 half load (once): 8192 / 128 = 64
        const __half* src = g_w + wbase + 131072 + (size_t)h * 128 * 512;
#pragma unroll
        for (int it = 0; it < 64; ++it) {
            int idx = tid + it * NT;
            int row = idx >> 6, seg = idx & 63;
            cpa(ws_s + row * (HP * 2) + seg * 16, src + row * 512 + seg * 8);
        }
        CP_COMMIT;
    }
    int a_row = ((lane >> 3) & 1) * 8 + (lane & 7);
    int a_col = (lane >> 4) * 8;
    unsigned aoff = (unsigned)((a_row * HP + a_col) * 2);
    int b_n = wn * 32 + (lane >> 4) * 8 + (lane & 7);
    int b_col = ((lane >> 3) & 1) * 8;
    unsigned bbase = ws_s + (unsigned)((b_n * HP + b_col) * 2);

    long t = blockIdx.y;
    if (t < ntiles) {
#pragma unroll
        for (int it = 0; it < 16; ++it) {
            int idx = tid + it * NT;
            int row = idx >> 6, seg = idx & 63;
            cpa(hs_s + row * (HP * 2) + seg * 16, g_h + ((size_t)t * TM2 + row) * H2 + seg * 8);
        }
        CP_COMMIT;
    }
    int buf = 0;
    for (; t < ntiles; t += gridDim.y, buf ^= 1) {
        long tn = t + gridDim.y;
        if (tn < ntiles) {
            unsigned db = hs_s + (buf ^ 1) * B_HS_BYTES;
#pragma unroll
            for (int it = 0; it < 16; ++it) {
                int idx = tid + it * NT;
                int row = idx >> 6, seg = idx & 63;
                cpa(db + row * (HP * 2) + seg * 16, g_h + ((size_t)tn * TM2 + row) * H2 + seg * 8);
            }
            CP_COMMIT; CP_WAIT1;
        } else { CP_WAIT0; }
        __syncthreads();

        unsigned hbuf = hs_s + buf * B_HS_BYTES;
        float acc[2][4][4];
#pragma unroll
        for (int mi = 0; mi < 2; ++mi)
#pragma unroll
            for (int nt = 0; nt < 4; ++nt)
#pragma unroll
                for (int i = 0; i < 4; ++i) acc[mi][nt][i] = 0.f;
#pragma unroll 4
        for (int kt = 0; kt < 32; ++kt) {
            unsigned koff = (unsigned)kt * 32;
            unsigned a[2][4], b[2][4];
            ldm4(a[0], hbuf + aoff + koff);
            ldm4(a[1], hbuf + aoff + 16 * HP * 2 + koff);
            ldm4(b[0], bbase + koff);
            ldm4(b[1], bbase + 16 * HP * 2 + koff);
#pragma unroll
            for (int mi = 0; mi < 2; ++mi)
#pragma unroll
                for (int ni = 0; ni < 2; ++ni) {
                    hmma(acc[mi][2 * ni],     a[mi], b[ni][0], b[ni][1]);
                    hmma(acc[mi][2 * ni + 1], a[mi], b[ni][2], b[ni][3]);
                }
        }
        // epilogue: bias + residual
        long base = t * TM2;
#pragma unroll
        for (int mi = 0; mi < 2; ++mi) {
#pragma unroll
            for (int nt = 0; nt < 4; ++nt) {
                int col = h * 128 + wn * 32 + nt * 8 + 2 * tig;
                float2 bb = *(const float2*)(bias2 + col);
                int r = mi * 16 + g;
                long gr0 = base + r, gr1 = gr0 + 8;
                if (gr0 < R) {
                    float2 x = *(const float2*)(X + gr0 * HH + col);
                    *(float2*)(out + gr0 * HH + col) =
                        make_float2(acc[mi][nt][0] + bb.x + x.x, acc[mi][nt][1] + bb.y + x.y);
                }
                if (gr1 < R) {
                    float2 x = *(const float2*)(X + gr1 * HH + col);
                    *(float2*)(out + gr1 * HH + col) =
                        make_float2(acc[mi][nt][2] + bb.x + x.x, acc[mi][nt][3] + bb.y + x.y);
                }
            }
        }
        __syncthreads();
    }
}

// ---------- launch ----------
extern "C" void kernel_launch(void* const* d_in, const int* in_sizes, int n_in,
                              void* d_out, int out_size) {
    const float* nodef = (const float*)d_in[0];
    const float* edgef = (const float*)d_in[1];
    const int*   batch = (const int*)d_in[2];
    int pb = n_in - 18;
    const float* P[18];
    for (int i = 0; i < 18; ++i) P[i] = (const float*)d_in[pb + i];

    float* out   = (float*)d_out;
    float* out_g = out;
    float* out_n = out + (size_t)GG * HH;
    float* out_e = out_n + (size_t)NNODE * HH;

    cudaFuncSetAttribute(gemm1_kernel, cudaFuncAttributeMaxDynamicSharedMemorySize, A_SMEM);
    cudaFuncSetAttribute(gemm2_kernel, cudaFuncAttributeMaxDynamicSharedMemorySize, B_SMEM);

    prep_kernel<<<3072, 256>>>(P[2], P[4], P[8], P[10], P[14], P[16]);
    seg_mean_kernel<<<GG, HH>>>(nodef, batch, NNODE);

    // node
    ln_kernel<<<(NNODE + 7) / 8, 256>>>(nodef, NNODE, P[0], P[1], 0);
    gemm1_kernel<<<dim3(2, 74), NT, A_SMEM>>>(NNODE, 313, 0, P[3]);
    gemm2_kernel<<<dim3(2, 74), NT, B_SMEM>>>(nodef, NNODE, 625, 0, P[5], out_n, 0);
    // global
    ln_kernel<<<8, 256>>>(nullptr, GG, P[6], P[7], 1);
    gemm1_kernel<<<dim3(2, 1), NT, A_SMEM>>>(GG, 1, 262144, P[9]);
    gemm2_kernel<<<dim3(2, 2), NT, B_SMEM>>>(nullptr, GG, 2, 262144, P[11], out_g, 1);
    // edge
    ln_kernel<<<NEDGE / 8, 256>>>(edgef, NEDGE, P[12], P[13], 0);
    gemm1_kernel<<<dim3(2, 74), NT, A_SMEM>>>(NEDGE, 5000, 524288, P[15]);
    gemm2_kernel<<<dim3(2, 74), NT, B_SMEM>>>(edgef, NEDGE, 10000, 524288, P[17], out_e, 0);
}